// round 10
// baseline (speedup 1.0000x reference)
#include <cuda_runtime.h>
#include <cstdint>

// LIF scan: X[B,C,H,W,T=16] fp32 -> spikes same shape.
// mem = mem*0.5 + x_t; s = (mem >= 1); mem = s ? 0 : mem
//
// R10: persistent kernel (one wave, grid = 152 SMs * 5 CTAs) with a per-warp
// grid-strided depth-2 cp.async pipeline. Each tile's copies are issued one
// full compute+store iteration before use, so the wait at loop top is ~free.
// Keeps the proven warp-local swizzled smem transpose + 16B/lane coalescing.

#define DECAY  0.5f
#define THRESH 1.0f
#define T_STEPS 16
#define THREADS 256
#define WARPS   (THREADS / 32)
#define F4_PER_TILE 128            // 32 neurons * 4 float4 = 2 KB
#define GRID_CTAS 760              // 152 SMs * 5 resident CTAs

__device__ __forceinline__ void stcs4(float4* p, float4 v) {
    asm volatile("st.global.cs.v4.f32 [%0], {%1,%2,%3,%4};"
                 :: "l"(p), "f"(v.x), "f"(v.y), "f"(v.z), "f"(v.w) : "memory");
}

__device__ __forceinline__ void cp_async16(void* smem_dst, const void* gmem_src) {
    unsigned int d;
    asm("{ .reg .u64 t; cvta.to.shared.u64 t, %1; cvt.u32.u64 %0, t; }"
        : "=r"(d) : "l"(smem_dst));
    asm volatile("cp.async.cg.shared.global [%0], [%1], 16;"
                 :: "r"(d), "l"(gmem_src) : "memory");
}
#define CP_COMMIT() asm volatile("cp.async.commit_group;" ::: "memory")
#define CP_WAIT1()  asm volatile("cp.async.wait_group 1;" ::: "memory")

// Swizzled float4 slot for (warp-local neuron n in 0..31, logical quarter j)
__device__ __forceinline__ int slot(int n, int j) {
    return n * 4 + (j ^ ((n ^ (n >> 2)) & 3));
}

__global__ void __launch_bounds__(THREADS)
lif_kernel(const float4* __restrict__ x4, float4* __restrict__ o4, int n_tiles) {
    __shared__ float4 sm[WARPS * 2 * F4_PER_TILE];

    const int tid  = threadIdx.x;
    const int lane = tid & 31;
    const int wid  = tid >> 5;
    float4* buf[2] = { sm + wid * 2 * F4_PER_TILE,
                       sm + wid * 2 * F4_PER_TILE + F4_PER_TILE };

    const int wglobal = blockIdx.x * WARPS + wid;       // global warp id
    const int wstride = GRID_CTAS * WARPS;              // total warps

    const int n   = lane;
    const int swz = (n ^ (n >> 2)) & 3;

    // ---- Prologue: prefetch first two tiles ----
    {
        long long t0 = wglobal;
        if (t0 < n_tiles) {
            const float4* src = x4 + (size_t)t0 * F4_PER_TILE;
#pragma unroll
            for (int i = 0; i < 4; i++) {
                int x = i * 32 + lane;
                cp_async16(&buf[0][slot(x >> 2, x & 3)], src + x);
            }
        }
        CP_COMMIT();
        long long t1 = (long long)wglobal + wstride;
        if (t1 < n_tiles) {
            const float4* src = x4 + (size_t)t1 * F4_PER_TILE;
#pragma unroll
            for (int i = 0; i < 4; i++) {
                int x = i * 32 + lane;
                cp_async16(&buf[1][slot(x >> 2, x & 3)], src + x);
            }
        }
        CP_COMMIT();
    }

    int cur = 0;
    for (long long tile = wglobal; tile < n_tiles; tile += wstride, cur ^= 1) {
        CP_WAIT1();           // current buffer's group complete
        __syncwarp();

        float4* tp = buf[cur];
        float4 q0 = tp[n * 4 + (0 ^ swz)];
        float4 q1 = tp[n * 4 + (1 ^ swz)];
        float4 q2 = tp[n * 4 + (2 ^ swz)];
        float4 q3 = tp[n * 4 + (3 ^ swz)];

        float f[T_STEPS] = { q0.x,q0.y,q0.z,q0.w, q1.x,q1.y,q1.z,q1.w,
                             q2.x,q2.y,q2.z,q2.w, q3.x,q3.y,q3.z,q3.w };
        float mem = 0.0f;
#pragma unroll
        for (int i = 0; i < T_STEPS; i++) {
            mem = fmaf(mem, DECAY, f[i]);
            bool fire = (mem >= THRESH);
            f[i] = fire ? 1.0f : 0.0f;
            mem  = fire ? 0.0f : mem;
        }

        tp[n * 4 + (0 ^ swz)] = make_float4(f[0],  f[1],  f[2],  f[3]);
        tp[n * 4 + (1 ^ swz)] = make_float4(f[4],  f[5],  f[6],  f[7]);
        tp[n * 4 + (2 ^ swz)] = make_float4(f[8],  f[9],  f[10], f[11]);
        tp[n * 4 + (3 ^ swz)] = make_float4(f[12], f[13], f[14], f[15]);
        __syncwarp();

        float4* dst = o4 + (size_t)tile * F4_PER_TILE;
#pragma unroll
        for (int i = 0; i < 4; i++) {
            int x = i * 32 + lane;
            stcs4(dst + x, tp[slot(x >> 2, x & 3)]);
        }
        __syncwarp();         // all lanes done reading cur before refill

        // Prefetch tile + 2*stride into cur
        long long tn = tile + 2LL * wstride;
        if (tn < n_tiles) {
            const float4* src = x4 + (size_t)tn * F4_PER_TILE;
#pragma unroll
            for (int i = 0; i < 4; i++) {
                int x = i * 32 + lane;
                cp_async16(&tp[slot(x >> 2, x & 3)], src + x);
            }
        }
        CP_COMMIT();          // always commit to keep group accounting uniform
    }
}

extern "C" void kernel_launch(void* const* d_in, const int* in_sizes, int n_in,
                              void* d_out, int out_size) {
    const float4* x4 = (const float4*)d_in[0];
    float4* o4 = (float4*)d_out;
    int n_total = in_sizes[0];                   // 67108864 floats
    int n_neurons = n_total / T_STEPS;           // 4194304
    int n_tiles = n_neurons / 32;                // 131072 warp tiles
    lif_kernel<<<GRID_CTAS, THREADS>>>(x4, o4, n_tiles);
}

// round 11
// speedup vs baseline: 1.1744x; 1.1744x over previous
#include <cuda_runtime.h>
#include <cstdint>

// LIF scan: X[B,C,H,W,T=16] fp32 -> spikes same shape.
// mem = mem*0.5 + x_t; s = (mem >= 1); mem = s ? 0 : mem
//
// FINAL (R9 structure, best kernel time 75.1us, DRAM 80.5%, ~7.15 TB/s eff):
//  - 16B/lane perfectly coalesced global access (LDGSTS.128 in, STG.128 out)
//  - warp-local XOR-swizzled smem transpose, bank-conflict-free both phases
//  - two tiles per warp, double-buffered cp.async (MLP=8, zero reg staging):
//    tile0 computed/stored while tile1's copies are still in flight
//  - warp-only synchronization; CTA waves pipelined by the HW scheduler
// Verified non-binding: occupancy, issue rate, barriers, L1/smem, all pipes.
// Bound: HBM read+write-mix ceiling (~89% of 8 TB/s spec).

#define DECAY  0.5f
#define THRESH 1.0f
#define T_STEPS 16
#define THREADS 256
#define WARPS   (THREADS / 32)
#define F4_PER_TILE 128            // 32 neurons * 4 float4 = 2 KB
#define F4_PER_WARP (2 * F4_PER_TILE)

__device__ __forceinline__ void cp_async16(void* smem_dst, const void* gmem_src) {
    unsigned int d;
    asm("{ .reg .u64 t; cvta.to.shared.u64 t, %1; cvt.u32.u64 %0, t; }"
        : "=r"(d) : "l"(smem_dst));
    asm volatile("cp.async.cg.shared.global [%0], [%1], 16;"
                 :: "r"(d), "l"(gmem_src) : "memory");
}

// Swizzled float4 slot for (warp-local neuron n in 0..31, logical quarter j)
__device__ __forceinline__ int slot(int n, int j) {
    return n * 4 + (j ^ ((n ^ (n >> 2)) & 3));
}

__device__ __forceinline__ void scan16(float* f) {
    float mem = 0.0f;
#pragma unroll
    for (int i = 0; i < T_STEPS; i++) {
        mem = fmaf(mem, DECAY, f[i]);
        bool fire = (mem >= THRESH);
        f[i] = fire ? 1.0f : 0.0f;
        mem  = fire ? 0.0f : mem;
    }
}

__global__ void __launch_bounds__(THREADS)
lif_kernel(const float4* __restrict__ x4, float4* __restrict__ o4) {
    __shared__ float4 sm[WARPS * F4_PER_WARP];

    const int tid  = threadIdx.x;
    const int lane = tid & 31;
    const int wid  = tid >> 5;
    float4* wsm = sm + wid * F4_PER_WARP;   // tile0 at +0, tile1 at +F4_PER_TILE

    const size_t base = (size_t)blockIdx.x * (THREADS * 8) + (size_t)wid * F4_PER_WARP;

    // ---- Front-batch both tiles' copies: 8 LDGSTS.128 per lane ----
#pragma unroll
    for (int i = 0; i < 4; i++) {
        int x = i * 32 + lane;
        cp_async16(&wsm[slot(x >> 2, x & 3)], x4 + base + x);
    }
    asm volatile("cp.async.commit_group;" ::: "memory");
#pragma unroll
    for (int i = 0; i < 4; i++) {
        int x = i * 32 + lane;
        cp_async16(&wsm[F4_PER_TILE + slot(x >> 2, x & 3)],
                   x4 + base + F4_PER_TILE + x);
    }
    asm volatile("cp.async.commit_group;" ::: "memory");

    const int n   = lane;
    const int swz = (n ^ (n >> 2)) & 3;

    // ================= Tile 0 (tile1 copies still in flight) =================
    asm volatile("cp.async.wait_group 1;" ::: "memory");
    __syncwarp();
    {
        float4 q0 = wsm[n * 4 + (0 ^ swz)];
        float4 q1 = wsm[n * 4 + (1 ^ swz)];
        float4 q2 = wsm[n * 4 + (2 ^ swz)];
        float4 q3 = wsm[n * 4 + (3 ^ swz)];
        float f[T_STEPS] = { q0.x,q0.y,q0.z,q0.w, q1.x,q1.y,q1.z,q1.w,
                             q2.x,q2.y,q2.z,q2.w, q3.x,q3.y,q3.z,q3.w };
        scan16(f);
        wsm[n * 4 + (0 ^ swz)] = make_float4(f[0],  f[1],  f[2],  f[3]);
        wsm[n * 4 + (1 ^ swz)] = make_float4(f[4],  f[5],  f[6],  f[7]);
        wsm[n * 4 + (2 ^ swz)] = make_float4(f[8],  f[9],  f[10], f[11]);
        wsm[n * 4 + (3 ^ swz)] = make_float4(f[12], f[13], f[14], f[15]);
        __syncwarp();
#pragma unroll
        for (int i = 0; i < 4; i++) {
            int x = i * 32 + lane;
            o4[base + x] = wsm[slot(x >> 2, x & 3)];
        }
    }

    // ================= Tile 1 =================
    asm volatile("cp.async.wait_group 0;" ::: "memory");
    __syncwarp();
    {
        float4* tp = wsm + F4_PER_TILE;
        float4 q0 = tp[n * 4 + (0 ^ swz)];
        float4 q1 = tp[n * 4 + (1 ^ swz)];
        float4 q2 = tp[n * 4 + (2 ^ swz)];
        float4 q3 = tp[n * 4 + (3 ^ swz)];
        float f[T_STEPS] = { q0.x,q0.y,q0.z,q0.w, q1.x,q1.y,q1.z,q1.w,
                             q2.x,q2.y,q2.z,q2.w, q3.x,q3.y,q3.z,q3.w };
        scan16(f);
        tp[n * 4 + (0 ^ swz)] = make_float4(f[0],  f[1],  f[2],  f[3]);
        tp[n * 4 + (1 ^ swz)] = make_float4(f[4],  f[5],  f[6],  f[7]);
        tp[n * 4 + (2 ^ swz)] = make_float4(f[8],  f[9],  f[10], f[11]);
        tp[n * 4 + (3 ^ swz)] = make_float4(f[12], f[13], f[14], f[15]);
        __syncwarp();
#pragma unroll
        for (int i = 0; i < 4; i++) {
            int x = i * 32 + lane;
            o4[base + F4_PER_TILE + x] = tp[slot(x >> 2, x & 3)];
        }
    }
}

extern "C" void kernel_launch(void* const* d_in, const int* in_sizes, int n_in,
                              void* d_out, int out_size) {
    const float4* x4 = (const float4*)d_in[0];
    float4* o4 = (float4*)d_out;
    int n_total = in_sizes[0];                   // 67108864 floats
    int n_neurons = n_total / T_STEPS;           // 4194304
    int blocks = n_neurons / (THREADS * 2);      // 8192
    lif_kernel<<<blocks, THREADS>>>(x4, o4);
}